// round 14
// baseline (speedup 1.0000x reference)
#include <cuda_runtime.h>
#include <cuda_fp16.h>
#include <cstdint>

#define K_DIM   4096
#define N_DIM   11008
#define BM      256
#define BN      128
#define BK      64
#define THREADS 256
#define KTILES  (K_DIM / BK)    // 64
#define NGROUPS (K_DIM / 128)   // 32

// smem (bytes): XOR-swizzled unpadded tiles, 128B rows
#define OFF_A 0                  // [2][256][64] half = 65536
#define OFF_B 65536              // [2][128][64] half = 32768
#define OFF_P 98304              // [2][8][128] int   =  8192
#define OFF_S 106496             // [32][128] half    =  8192
#define SMEM_BYTES 114688        // 112 KB -> 2 CTAs/SM

// fp16 copy of x (one-time convert pre-pass)
__device__ __half x16g[(size_t)4096 * (size_t)K_DIM];

static __device__ __forceinline__ unsigned smem_u32(const void* p) {
    return (unsigned)__cvta_generic_to_shared(p);
}
static __device__ __forceinline__ void cp_async16(unsigned dst, const void* src) {
    asm volatile("cp.async.cg.shared.global [%0], [%1], 16;\n" :: "r"(dst), "l"(src));
}
// byte offset of 16B chunk `ch` in row `r` of a swizzled tile (8 chunks/row)
static __device__ __forceinline__ unsigned tswz(int r, int ch) {
    return (unsigned)(r * 128 + ((ch ^ (r & 7)) << 4));
}

__global__ void __launch_bounds__(256)
convert_kernel(const float* __restrict__ x) {
    size_t i = ((size_t)blockIdx.x * 256 + threadIdx.x) * 4;
    float4 v = *reinterpret_cast<const float4*>(x + i);
    __half2 h0 = __floats2half2_rn(v.x, v.y);
    __half2 h1 = __floats2half2_rn(v.z, v.w);
    uint2 p;
    p.x = *reinterpret_cast<unsigned*>(&h0);
    p.y = *reinterpret_cast<unsigned*>(&h1);
    *reinterpret_cast<uint2*>(x16g + i) = p;
}

__global__ void __launch_bounds__(THREADS, 2)
quantlinear_kernel(const int*   __restrict__ packed,
                   const float* __restrict__ scales,
                   const float* __restrict__ bias,
                   float*       __restrict__ out)
{
    extern __shared__ char smem[];
    char*   Ab = smem + OFF_A;
    char*   Bb = smem + OFF_B;
    int*    Ps = reinterpret_cast<int*>(smem + OFF_P);
    __half* Ss = reinterpret_cast<__half*>(smem + OFF_S);

    const int tid    = threadIdx.x;
    const int lane   = tid & 31;
    const int wid    = tid >> 5;
    const int warp_m = wid & 3;      // 0..3 -> 64 rows each
    const int warp_n = wid >> 2;     // 0..1 -> 64 cols each
    const int m0 = blockIdx.y * BM;
    const int n0 = blockIdx.x * BN;

    // ---- preload scale groups for this N-slab ----
    for (int i = tid; i < NGROUPS * BN; i += THREADS) {
        int g = i >> 7, n = i & 127;
        Ss[i] = __float2half(scales[(size_t)g * N_DIM + n0 + n]);
    }

    float acc[4][8][4];
    #pragma unroll
    for (int mi = 0; mi < 4; mi++)
        #pragma unroll
        for (int ni = 0; ni < 8; ni++)
            #pragma unroll
            for (int j = 0; j < 4; j++) acc[mi][ni][j] = 0.f;

    // ---- issue tile 0 ----
    {
        #pragma unroll
        for (int i = 0; i < 8; i++) {                 // A: 256 rows x 8 chunks
            int c = i * THREADS + tid;
            int m = c >> 3, ch = c & 7;
            cp_async16(smem_u32(Ab + tswz(m, ch)),
                       x16g + (size_t)(m0 + m) * K_DIM + ch * 8);
        }
        {                                             // P: 8x128 int = 256 x 16B
            int kw = tid >> 5, n4 = (tid & 31) * 4;
            cp_async16(smem_u32(Ps + kw * 128 + n4),
                       packed + (size_t)kw * N_DIM + n0 + n4);
        }
        asm volatile("cp.async.commit_group;\n" ::: "memory");
    }

    const int dq_n = tid & 127;
    const __half2 h1032 = __half2half2(__ushort_as_half(0x6408));  // 1024 + 8

    for (int t = 0; t < KTILES; t++) {
        const int cur = t & 1;

        asm volatile("cp.async.wait_group 0;\n" ::: "memory");
        __syncthreads();   // A(t), P(t) visible; mma(t-1) complete everywhere

        // ---- dequant packed tile -> B[cur] (exact (q-8), then *s) ----
        {
            const int* Pb = Ps + cur * 8 * BN;
            char* Bt = Bb + cur * 16384;
            const __half2 s2 = __half2half2(Ss[(t >> 1) * BN + dq_n]);
            #pragma unroll
            for (int i = 0; i < 4; i++) {
                const int kw = 2 * i + (tid >> 7);
                int w = Pb[kw * BN + dq_n];
                uint4 ov;
                unsigned* op = reinterpret_cast<unsigned*>(&ov);
                #pragma unroll
                for (int j = 0; j < 4; j++) {
                    unsigned tt = ((unsigned)w) >> (8 * j);
                    unsigned bits = (tt & 0xFu) | ((tt & 0xF0u) << 12) | 0x64006400u;
                    __half2 h2 = *reinterpret_cast<__half2*>(&bits);
                    __half2 r  = __hmul2(__hsub2(h2, h1032), s2);
                    op[j] = *reinterpret_cast<unsigned*>(&r);
                }
                *reinterpret_cast<uint4*>(Bt + tswz(dq_n, kw)) = ov;
            }
        }

        // ---- prefetch tile t+1 ----
        if (t + 1 < KTILES) {
            const int nb = cur ^ 1;
            const size_t kt = (size_t)(t + 1) * BK;
            #pragma unroll
            for (int i = 0; i < 8; i++) {
                int c = i * THREADS + tid;
                int m = c >> 3, ch = c & 7;
                cp_async16(smem_u32(Ab + nb * 32768 + tswz(m, ch)),
                           x16g + (size_t)(m0 + m) * K_DIM + kt + ch * 8);
            }
            {
                int kw = tid >> 5, n4 = (tid & 31) * 4;
                cp_async16(smem_u32(Ps + nb * 8 * BN + kw * 128 + n4),
                           packed + (size_t)((t + 1) * 8 + kw) * N_DIM + n0 + n4);
            }
            asm volatile("cp.async.commit_group;\n" ::: "memory");
        }
        __syncthreads();   // B[cur] visible

        // ---- mma over the 256x128x64 tile, warp tile 64x64 ----
        {
            char* At = Ab + cur * 32768;
            char* Bt = Bb + cur * 16384;
            const int ar = warp_m * 64 + (lane & 7) + ((lane >> 3) & 1) * 8;
            const int ac = (lane >> 4) & 1;           // chunk offset within k16
            const int br = warp_n * 64 + (lane & 7) + ((lane >> 4) & 1) * 8;
            const int bc = (lane >> 3) & 1;

            #pragma unroll
            for (int kk = 0; kk < 4; kk++) {
                unsigned a[4][4];
                #pragma unroll
                for (int mi = 0; mi < 4; mi++) {
                    int r = ar + mi * 16;
                    unsigned addr = smem_u32(At + tswz(r, kk * 2 + ac));
                    asm volatile("ldmatrix.sync.aligned.m8n8.x4.shared.b16 {%0,%1,%2,%3}, [%4];\n"
                                 : "=r"(a[mi][0]), "=r"(a[mi][1]), "=r"(a[mi][2]), "=r"(a[mi][3])
                                 : "r"(addr));
                }
                unsigned b[8][2];
                #pragma unroll
                for (int ni4 = 0; ni4 < 4; ni4++) {
                    int r = br + ni4 * 16;
                    unsigned addr = smem_u32(Bt + tswz(r, kk * 2 + bc));
                    asm volatile("ldmatrix.sync.aligned.m8n8.x4.shared.b16 {%0,%1,%2,%3}, [%4];\n"
                                 : "=r"(b[2*ni4][0]), "=r"(b[2*ni4][1]),
                                   "=r"(b[2*ni4+1][0]), "=r"(b[2*ni4+1][1])
                                 : "r"(addr));
                }
                #pragma unroll
                for (int mi = 0; mi < 4; mi++)
                    #pragma unroll
                    for (int ni = 0; ni < 8; ni++) {
                        asm volatile(
                            "mma.sync.aligned.m16n8k16.row.col.f32.f16.f16.f32 "
                            "{%0,%1,%2,%3}, {%4,%5,%6,%7}, {%8,%9}, {%0,%1,%2,%3};\n"
                            : "+f"(acc[mi][ni][0]), "+f"(acc[mi][ni][1]),
                              "+f"(acc[mi][ni][2]), "+f"(acc[mi][ni][3])
                            : "r"(a[mi][0]), "r"(a[mi][1]), "r"(a[mi][2]), "r"(a[mi][3]),
                              "r"(b[ni][0]), "r"(b[ni][1]));
                    }
            }
        }
    }

    // ---- epilogue: add bias (fp32), store fp32 ----
    #pragma unroll
    for (int mi = 0; mi < 4; mi++) {
        #pragma unroll
        for (int ni = 0; ni < 8; ni++) {
            int r = m0 + warp_m * 64 + mi * 16 + (lane >> 2);
            int c = n0 + warp_n * 64 + ni * 8 + 2 * (lane & 3);
            float2 bb = *reinterpret_cast<const float2*>(bias + c);
            float2 v0 = make_float2(acc[mi][ni][0] + bb.x, acc[mi][ni][1] + bb.y);
            float2 v1 = make_float2(acc[mi][ni][2] + bb.x, acc[mi][ni][3] + bb.y);
            *reinterpret_cast<float2*>(out + (size_t)r * N_DIM + c) = v0;
            *reinterpret_cast<float2*>(out + (size_t)(r + 8) * N_DIM + c) = v1;
        }
    }
}

extern "C" void kernel_launch(void* const* d_in, const int* in_sizes, int n_in,
                              void* d_out, int out_size) {
    const float* x      = (const float*)d_in[0];
    const int*   packed = (const int*)d_in[1];
    const float* scales = (const float*)d_in[2];
    const float* bias   = (const float*)d_in[3];
    float*       out    = (float*)d_out;

    const int M = in_sizes[0] / K_DIM;   // 4096

    // 1) x fp32 -> fp16 scratch
    convert_kernel<<<(M * K_DIM) / 1024, 256>>>(x);

    // 2) fused dequant GEMM
    cudaFuncSetAttribute(quantlinear_kernel,
                         cudaFuncAttributeMaxDynamicSharedMemorySize, SMEM_BYTES);
    dim3 grid(N_DIM / BN, M / BM);       // (86, 16)
    quantlinear_kernel<<<grid, THREADS, SMEM_BYTES>>>(packed, scales, bias, out);
}